// round 3
// baseline (speedup 1.0000x reference)
#include <cuda_runtime.h>

// Scalar damped-Newton minimization of a degree-6 polynomial (latency-optimized).
// Inputs: d_in[0] = poly (7 x float32, lowest-degree first), d_in[1] = x_init (1 x f32)
// Output: 1 x float32 = x_min.
//
// Semantics match the JAX lax.while_loop exactly in iteration structure:
//   while (g2 > 1e-12 && it < 100) { g=p'(x); h=p''(x);
//       step = h>0 ? g/h : 0.1*g; x -= step; g2 = p'(x)^2; it++ }
// Restructured so p'(x) is evaluated once per iteration (carried forward),
// with Estrin evaluation and fast division to shorten the dependent chain.

#define MAX_ITER 100
#define GRAD_SQ_TOL 1e-12f

__global__ void polymin_kernel(const float* __restrict__ poly,
                               const float* __restrict__ x_init,
                               float* __restrict__ out) {
    float c1 = poly[1], c2 = poly[2], c3 = poly[3];
    float c4 = poly[4], c5 = poly[5], c6 = poly[6];

    // p'(x) coefficients (degree 5): d1[k] = poly[k+1]*(k+1)
    float d1_0 = c1;
    float d1_1 = c2 * 2.0f;
    float d1_2 = c3 * 3.0f;
    float d1_3 = c4 * 4.0f;
    float d1_4 = c5 * 5.0f;
    float d1_5 = c6 * 6.0f;

    // p''(x) coefficients (degree 4): d2[k] = d1[k+1]*(k+1)
    float d2_0 = d1_1;
    float d2_1 = d1_2 * 2.0f;
    float d2_2 = d1_3 * 3.0f;
    float d2_3 = d1_4 * 4.0f;
    float d2_4 = d1_5 * 5.0f;

    float x = x_init[0];

    // g = p'(x) via Estrin: 3 dependent levels instead of 5.
    float x2 = x * x;
    float g  = fmaf(fmaf(fmaf(d1_5, x, d1_4), x2, fmaf(d1_3, x, d1_2)), x2,
                    fmaf(d1_1, x, d1_0));

    #pragma unroll 1
    for (int it = 0; it < MAX_ITER; ++it) {
        // h = p''(x), Estrin (x2 already available)
        float h = fmaf(fmaf(fmaf(d2_4, x, d2_3), x, d2_2), x2,
                       fmaf(d2_1, x, d2_0));

        // step = h>0 ? g/h : 0.1*g   (fast division: MUFU.RCP + FMUL)
        float step = (h > 0.0f) ? __fdividef(g, h) : (0.1f * g);
        x = x - step;

        // g = p'(x_new), carried into next iteration's step
        x2 = x * x;
        g  = fmaf(fmaf(fmaf(d1_5, x, d1_4), x2, fmaf(d1_3, x, d1_2)), x2,
                  fmaf(d1_1, x, d1_0));

        if (!(g * g > GRAD_SQ_TOL)) break;
    }

    out[0] = x;
}

extern "C" void kernel_launch(void* const* d_in, const int* in_sizes, int n_in,
                              void* d_out, int out_size) {
    const float* poly   = (const float*)d_in[0];
    const float* x_init = (const float*)d_in[1];
    polymin_kernel<<<1, 1>>>(poly, x_init, (float*)d_out);
}

// round 4
// speedup vs baseline: 1.0670x; 1.0670x over previous
#include <cuda_runtime.h>

// Scalar damped-Newton minimization of a degree-6 polynomial.
// Inputs: d_in[0] = poly (7 x float32, lowest-degree first), d_in[1] = x_init (1 x f32)
// Output: 1 x float32 = x_min.
//
// Same fixed point as the JAX lax.while_loop:
//   while (g2 > 1e-12 && it < 100) { g=p'(x); h=p''(x);
//       step = h>0 ? g/h : 0.1*g; x -= step; g2 = p'(x)^2; it++ }
//
// Latency-bound single-thread kernel; the measured time is dominated by CTA
// launch overhead. This version minimizes startup latency: 3 vectorized LDGs
// (float4 + float2 + float) issued back-to-back (MLP=4 incl. x_init), with
// derivative-coefficient FMULs hidden under the load shadow.

#define MAX_ITER 100
#define GRAD_SQ_TOL 1e-12f

__global__ void polymin_kernel(const float4* __restrict__ poly4,
                               const float* __restrict__ x_init,
                               float* __restrict__ out) {
    // poly base is allocation-aligned: [0..3] as float4, [4..5] as float2, [6] scalar.
    const float2* poly2 = (const float2*)poly4;
    const float*  polyf = (const float*)poly4;

    float4 pA = poly4[0];        // c0..c3
    float2 pB = poly2[2];        // c4, c5
    float  c6 = polyf[6];
    float  x  = x_init[0];

    // p'(x) coefficients (degree 5)
    float d1_0 = pA.y;
    float d1_1 = pA.z * 2.0f;
    float d1_2 = pA.w * 3.0f;
    float d1_3 = pB.x * 4.0f;
    float d1_4 = pB.y * 5.0f;
    float d1_5 = c6   * 6.0f;

    // p''(x) coefficients (degree 4)
    float d2_0 = d1_1;
    float d2_1 = d1_2 * 2.0f;
    float d2_2 = d1_3 * 3.0f;
    float d2_3 = d1_4 * 4.0f;
    float d2_4 = d1_5 * 5.0f;

    // g = p'(x) via Estrin (3 dependent levels)
    float x2 = x * x;
    float g  = fmaf(fmaf(fmaf(d1_5, x, d1_4), x2, fmaf(d1_3, x, d1_2)), x2,
                    fmaf(d1_1, x, d1_0));

    #pragma unroll 1
    for (int it = 0; it < MAX_ITER; ++it) {
        // h = p''(x), Estrin
        float h = fmaf(fmaf(fmaf(d2_4, x, d2_3), x, d2_2), x2,
                       fmaf(d2_1, x, d2_0));

        float step = (h > 0.0f) ? __fdividef(g, h) : (0.1f * g);
        x = x - step;

        // carried gradient: g = p'(x_new)
        x2 = x * x;
        g  = fmaf(fmaf(fmaf(d1_5, x, d1_4), x2, fmaf(d1_3, x, d1_2)), x2,
                  fmaf(d1_1, x, d1_0));

        if (!(g * g > GRAD_SQ_TOL)) break;
    }

    out[0] = x;
}

extern "C" void kernel_launch(void* const* d_in, const int* in_sizes, int n_in,
                              void* d_out, int out_size) {
    polymin_kernel<<<1, 1>>>((const float4*)d_in[0], (const float*)d_in[1],
                             (float*)d_out);
}